// round 5
// baseline (speedup 1.0000x reference)
#include <cuda_runtime.h>

#define H 32
#define WPB 7           // warps per block; each warp = 2 batch rows
#define THREADS (WPB*32)
#define CHUNK 16        // deferred-output chunk
#define RSTRIDE 48      // ring: row B offset (floats) -> 16-bank shift
#define TSTRIDE 560     // hT: row B offset (floats), 560%32==16 -> 16-bank shift

typedef unsigned long long ull;

// ---------- packed f32x2 helpers (sm_103a dual FP32 pipe) ----------
__device__ __forceinline__ ull ffma2(ull a, ull b, ull c) {
    ull d;
    asm("fma.rn.f32x2 %0, %1, %2, %3;" : "=l"(d) : "l"(a), "l"(b), "l"(c));
    return d;
}
__device__ __forceinline__ ull addf2(ull a, ull b) {
    ull d;
    asm("add.rn.f32x2 %0, %1, %2;" : "=l"(d) : "l"(a), "l"(b));
    return d;
}
__device__ __forceinline__ ull mulf2(ull a, ull b) {
    ull d;
    asm("mul.rn.f32x2 %0, %1, %2;" : "=l"(d) : "l"(a), "l"(b));
    return d;
}
__device__ __forceinline__ float hsum2(ull a) {
    float lo, hi;
    asm("mov.b64 {%0, %1}, %2;" : "=f"(lo), "=f"(hi) : "l"(a));
    return lo + hi;
}
__device__ __forceinline__ float tanh_ap(float x) {
    float r; asm("tanh.approx.f32 %0, %1;" : "=f"(r) : "f"(x)); return r;
}
__device__ __forceinline__ ull pack2(float lo, float hi) {
    ull d;
    asm("mov.b64 %0, {%1, %2};" : "=l"(d) : "f"(lo), "f"(hi));
    return d;
}

// One warp = 2 batch rows. lane = hidden unit u for BOTH rows -> weight
// registers shared across rows. grid=147x7 warps covers 1024 row pairs,
// single wave, all SMs.
__global__ void __launch_bounds__(THREADS, 1)
gru_warp_kernel(const float* __restrict__ x,     // [B,T]
                const float* __restrict__ h0,    // [B,H]
                const float* __restrict__ W_ih,  // [3H] (I=1)
                const float* __restrict__ W_hh,  // [3H,H]
                const float* __restrict__ b_ih,  // [3H]
                const float* __restrict__ b_hh,  // [3H]
                const float* __restrict__ W_out, // [H]
                const float* __restrict__ b_out, // [1]
                float* __restrict__ y,           // [B,T]
                float* __restrict__ hn,          // [B,H]
                int B, int T)
{
    __shared__ __align__(16) float ring[WPB][2][2 * RSTRIDE]; // h bcast, 2 rows, dbl-buf
    __shared__ float hT[WPB][2 * TSTRIDE];                    // per-row 32x17 history
    __shared__ float wout_s[H];

    const int lane = threadIdx.x & 31;   // hidden unit u
    const int w    = threadIdx.x >> 5;
    const int npairs = B >> 1;
    const int p    = blockIdx.x * WPB + w;

    if (threadIdx.x < H) wout_s[threadIdx.x] = W_out[threadIdx.x];
    __syncthreads();
    if (p >= npairs) return;

    const int rowA = 2 * p;
    const int rowB = 2 * p + 1;

    // ---- recurrent weights for unit u (3 gate rows), shared by both rows.
    //      r/z rows pre-scaled by 0.5: sigmoid(a) = 0.5 + 0.5*tanh(a/2). ----
    ull Wr[16], Wz[16], Wn[16];
    {
        const ull HALF2 = 0x3F0000003F000000ull;  // (0.5f, 0.5f)
        const ull* wr = (const ull*)(W_hh + (size_t)lane * H);
        const ull* wz = (const ull*)(W_hh + (size_t)(H + lane) * H);
        const ull* wn = (const ull*)(W_hh + (size_t)(2 * H + lane) * H);
        #pragma unroll
        for (int k = 0; k < 16; k++) {
            Wr[k] = mulf2(wr[k], HALF2);
            Wz[k] = mulf2(wz[k], HALF2);
            Wn[k] = wn[k];
        }
    }
    const float wihr = 0.5f * W_ih[lane];
    const float wihz = 0.5f * W_ih[H + lane];
    const float wihn = W_ih[2 * H + lane];
    // biases folded into accumulator inits (lo half of packed pair)
    const ull ir = pack2(0.5f * (b_ih[lane] + b_hh[lane]), 0.0f);
    const ull iz = pack2(0.5f * (b_ih[H + lane] + b_hh[H + lane]), 0.0f);
    const ull in_ = pack2(b_hh[2 * H + lane], 0.0f);   // n hidden bias (inside r*)
    const float bin = b_ih[2 * H + lane];
    const float bo  = b_out[0];

    float hA = h0[(size_t)rowA * H + lane];
    float hB = h0[(size_t)rowB * H + lane];
    ring[w][1][lane]           = hA;     // step 0 reads parity 1
    ring[w][1][RSTRIDE + lane] = hB;
    __syncwarp();

    const float* xrowA = x + (size_t)rowA * T;
    const float* xrowB = x + (size_t)rowB * T;
    float*       yrowA = y + (size_t)rowA * T;
    float*       yrowB = y + (size_t)rowB * T;
    float* hTw = &hT[w][0];

    const int tl = lane & 15;            // timestep within chunk (y-phase / x-stage)
    const int rsel = lane >> 4;          // 0: row A duty, 1: row B duty

    for (int t0 = 0; t0 < T; t0 += CHUNK) {
        // lanes 0..15 stage row A inputs, lanes 16..31 stage row B inputs
        const float xv = (rsel == 0) ? xrowA[t0 + tl] : xrowB[t0 + tl];

        #pragma unroll 2
        for (int s = 0; s < CHUNK; s++) {
            const int rd = (s & 1) ^ 1;
            const int wb = (s & 1);

            const float xtA = __shfl_sync(0xffffffffu, xv, s);       // lane s
            const float xtB = __shfl_sync(0xffffffffu, xv, 16 + s);  // lane 16+s

            const ulonglong2* hpA = (const ulonglong2*)&ring[w][rd][0];
            const ulonglong2* hpB = (const ulonglong2*)&ring[w][rd][RSTRIDE];

            // 12 independent 8-deep FFMA2 chains (3 gates x 2 halves x 2 rows)
            ull arA = ir, azA = iz, anA = in_;
            ull arB = ir, azB = iz, anB = in_;
            ull arA1 = 0ull, azA1 = 0ull, anA1 = 0ull;
            ull arB1 = 0ull, azB1 = 0ull, anB1 = 0ull;
            #pragma unroll
            for (int q = 0; q < 8; q++) {
                const ulonglong2 hvA = hpA[q];
                const ulonglong2 hvB = hpB[q];
                arA  = ffma2(hvA.x, Wr[2 * q],     arA);
                azA  = ffma2(hvA.x, Wz[2 * q],     azA);
                anA  = ffma2(hvA.x, Wn[2 * q],     anA);
                arB  = ffma2(hvB.x, Wr[2 * q],     arB);
                azB  = ffma2(hvB.x, Wz[2 * q],     azB);
                anB  = ffma2(hvB.x, Wn[2 * q],     anB);
                arA1 = ffma2(hvA.y, Wr[2 * q + 1], arA1);
                azA1 = ffma2(hvA.y, Wz[2 * q + 1], azA1);
                anA1 = ffma2(hvA.y, Wn[2 * q + 1], anA1);
                arB1 = ffma2(hvB.y, Wr[2 * q + 1], arB1);
                azB1 = ffma2(hvB.y, Wz[2 * q + 1], azB1);
                anB1 = ffma2(hvB.y, Wn[2 * q + 1], anB1);
            }
            // row A
            {
                const float gr = hsum2(addf2(arA, arA1));
                const float gz = hsum2(addf2(azA, azA1));
                const float gn = hsum2(addf2(anA, anA1));
                const float rg = fmaf(0.5f, tanh_ap(fmaf(xtA, wihr, gr)), 0.5f);
                const float zg = fmaf(0.5f, tanh_ap(fmaf(xtA, wihz, gz)), 0.5f);
                const float ng = tanh_ap(fmaf(rg, gn, fmaf(xtA, wihn, bin)));
                hA = fmaf(zg, hA - ng, ng);
            }
            // row B
            {
                const float gr = hsum2(addf2(arB, arB1));
                const float gz = hsum2(addf2(azB, azB1));
                const float gn = hsum2(addf2(anB, anB1));
                const float rg = fmaf(0.5f, tanh_ap(fmaf(xtB, wihr, gr)), 0.5f);
                const float zg = fmaf(0.5f, tanh_ap(fmaf(xtB, wihz, gz)), 0.5f);
                const float ng = tanh_ap(fmaf(rg, gn, fmaf(xtB, wihn, bin)));
                hB = fmaf(zg, hB - ng, ng);
            }

            ring[w][wb][lane]           = hA;
            ring[w][wb][RSTRIDE + lane] = hB;
            hTw[17 * lane + s]           = hA;   // banks 17u+s : conflict-free
            hTw[TSTRIDE + 17 * lane + s] = hB;   // +560 -> 16-bank shift, cf
            __syncwarp();
        }

        // Deferred y: lanes 0..15 -> row A step tl, lanes 16..31 -> row B step tl.
        // Bank check: rowA lanes use (17j+tl)%32 over tl=0..15; rowB adds 16.
        float acc = 0.0f;
        const float* hsrc = hTw + rsel * TSTRIDE;
        #pragma unroll
        for (int j = 0; j < H; j++)
            acc = fmaf(hsrc[17 * j + tl], wout_s[j], acc);
        if (rsel == 0) yrowA[t0 + tl] = acc + bo;
        else           yrowB[t0 + tl] = acc + bo;
        __syncwarp();                          // hT WAR before next chunk
    }

    hn[(size_t)rowA * H + lane] = hA;
    hn[(size_t)rowB * H + lane] = hB;
}

extern "C" void kernel_launch(void* const* d_in, const int* in_sizes, int n_in,
                              void* d_out, int out_size) {
    const float* x     = (const float*)d_in[0];   // [B,T,1]
    const float* h0    = (const float*)d_in[1];   // [1,B,H]
    const float* W_ih  = (const float*)d_in[2];   // [3H,1]
    const float* W_hh  = (const float*)d_in[3];   // [3H,H]
    const float* b_ih  = (const float*)d_in[4];   // [3H]
    const float* b_hh  = (const float*)d_in[5];   // [3H]
    const float* W_out = (const float*)d_in[6];   // [1,H]
    const float* b_out = (const float*)d_in[7];   // [1]
    float* out = (float*)d_out;

    const int B = in_sizes[1] / H;                // 2048
    const int T = in_sizes[0] / B;                // 1024

    float* y  = out;                              // [B,T]
    float* hn = out + (size_t)B * T;              // [B,H]

    const int npairs = B / 2;                     // 1024
    const int grid = (npairs + WPB - 1) / WPB;    // 147 -> all SMs, single wave
    gru_warp_kernel<<<grid, THREADS>>>(x, h0, W_ih, W_hh, b_ih, b_hh,
                                       W_out, b_out, y, hn, B, T);
}